// round 12
// baseline (speedup 1.0000x reference)
#include <cuda_runtime.h>
#include <cuda_fp16.h>

// ---------------- problem constants ----------------------------------------
#define NMAX   100000
#define EMAX   3200000
#define FEATS  512
#define HIDDEN 64
#define CLASSES 32
#define SCAN_CHUNK 1024
#define MAX_CHUNKS ((NMAX + SCAN_CHUNK - 1) / SCAN_CHUNK)

// ---------------- scratch (static device memory; no allocation) ------------
__device__ int    g_deg[NMAX];
__device__ int    g_rowptr[NMAX + 1];     // doubles as fill cursor
__device__ int    g_bsum[MAX_CHUNKS];
__device__ int    g_boff[MAX_CHUNKS];
__device__ int    g_csrs[EMAX];           // src only (u-space: no weights)
__device__ float  g_rinv[NMAX];
__device__ float2 g_coef[NMAX];           // {0.9/deg, sqrt(deg)}
__device__ float4 g_hidden[(size_t)NMAX * 16];  // 64 hidden
__device__ float4 g_h0u[(size_t)NMAX * 8];      // 0.1 * rinv * h0 (fp32)
__device__ uint2  g_uhA[(size_t)NMAX * 8];      // u as half4 chunks (64 B/row)
__device__ uint2  g_uhB[(size_t)NMAX * 8];

// ---------------- f32x2 packed-FMA helpers (sm_100+) ------------------------
__device__ __forceinline__ unsigned long long pack2(float lo, float hi) {
    unsigned long long r;
    asm("mov.b64 %0, {%1, %2};" : "=l"(r) : "f"(lo), "f"(hi));
    return r;
}
__device__ __forceinline__ void ffma2(unsigned long long& d,
                                      unsigned long long a,
                                      unsigned long long b) {
    asm("fma.rn.f32x2 %0, %1, %2, %0;" : "+l"(d) : "l"(a), "l"(b));
}
__device__ __forceinline__ float2 unpack2(unsigned long long v) {
    float2 f;
    asm("mov.b64 {%0, %1}, %2;" : "=f"(f.x), "=f"(f.y) : "l"(v));
    return f;
}

// half4 (uint2) -> accumulate into float4
__device__ __forceinline__ void acc4(float4& a, uint2 v) {
    float2 p;
    p = __half22float2(*(__half2*)&v.x); a.x += p.x; a.y += p.y;
    p = __half22float2(*(__half2*)&v.y); a.z += p.x; a.w += p.y;
}
__device__ __forceinline__ uint2 pack4(float4 a) {
    uint2 r;
    *(__half2*)&r.x = __floats2half2_rn(a.x, a.y);
    *(__half2*)&r.y = __floats2half2_rn(a.z, a.w);
    return r;
}

// ---------------- setup kernels ---------------------------------------------
__global__ void zero_kernel(int n) {
    int i = blockIdx.x * blockDim.x + threadIdx.x;
    if (i < n) g_deg[i] = 0;
}

__global__ void deg_kernel(const int* __restrict__ edges, int E) {
    int i = blockIdx.x * blockDim.x + threadIdx.x;
    if (i < E) atomicAdd(&g_deg[edges[E + i]], 1);
}

__global__ void coef_kernel(int n) {
    int i = blockIdx.x * blockDim.x + threadIdx.x;
    if (i >= n) return;
    float fd = (float)max(g_deg[i], 1);
    g_rinv[i] = rsqrtf(fd);
    g_coef[i] = make_float2(0.9f / fd, sqrtf(fd));
}

// ---- decoupled scan: phase 1 — per-block exclusive scan + block sum --------
__global__ void scan_block_kernel(int n) {
    __shared__ int wsum[32];
    int tid = threadIdx.x, lane = tid & 31, wid = tid >> 5;
    int i = blockIdx.x * SCAN_CHUNK + tid;
    int v = (i < n) ? g_deg[i] : 0;
    int s = v;
    #pragma unroll
    for (int o = 1; o < 32; o <<= 1) {
        int t = __shfl_up_sync(0xffffffffu, s, o);
        if (lane >= o) s += t;
    }
    if (lane == 31) wsum[wid] = s;
    __syncthreads();
    if (wid == 0) {
        int ws = wsum[lane];
        #pragma unroll
        for (int o = 1; o < 32; o <<= 1) {
            int t = __shfl_up_sync(0xffffffffu, ws, o);
            if (lane >= o) ws += t;
        }
        wsum[lane] = ws;
    }
    __syncthreads();
    int incl = s + (wid ? wsum[wid - 1] : 0);
    if (i < n) g_rowptr[i] = incl - v;
    if (tid == SCAN_CHUNK - 1) g_bsum[blockIdx.x] = incl;
}

__global__ void scan_sums_kernel(int nb, int n) {
    int acc = 0;
    for (int b = 0; b < nb; b++) {
        g_boff[b] = acc;
        acc += g_bsum[b];
    }
    g_rowptr[n] = acc;
}

__global__ void scan_add_kernel(int n) {
    int i = blockIdx.x * blockDim.x + threadIdx.x;
    if (i < n) g_rowptr[i] += g_boff[i >> 10];
}

__global__ void fill_kernel(const int* __restrict__ edges, int E) {
    int i = blockIdx.x * blockDim.x + threadIdx.x;
    if (i >= E) return;
    int s = edges[i];
    int d = edges[E + i];
    int pos = atomicAdd(&g_rowptr[d], 1);
    g_csrs[pos] = s;
}

// ---------------- MLP layer 1: hidden = relu(x @ W1 + b1) -------------------
__global__ __launch_bounds__(256, 2)
void mlp1_kernel(const float* __restrict__ x,
                 const float* __restrict__ W1,
                 const float* __restrict__ b1, int n) {
    __shared__ float As[16][256];
    __shared__ float Ws[16][64];
    int tid = threadIdx.x;
    int tx  = tid & 7;
    int ty  = tid >> 3;
    int bn  = blockIdx.x * 256;

    int anode = tid >> 2;
    int ak    = (tid & 3) * 4;
    int wk    = tid >> 4;
    int wc    = (tid & 15) * 4;

    unsigned long long acc[8][4];
    #pragma unroll
    for (int i = 0; i < 8; i++)
        #pragma unroll
        for (int j = 0; j < 4; j++) acc[i][j] = 0ULL;

    for (int k0 = 0; k0 < FEATS; k0 += 16) {
        #pragma unroll
        for (int r = 0; r < 4; r++) {
            int nd = anode + r * 64;
            int node = bn + nd;
            float4 av = make_float4(0.f, 0.f, 0.f, 0.f);
            if (node < n)
                av = *(const float4*)&x[(size_t)node * FEATS + k0 + ak];
            As[ak + 0][nd] = av.x;
            As[ak + 1][nd] = av.y;
            As[ak + 2][nd] = av.z;
            As[ak + 3][nd] = av.w;
        }
        *(float4*)&Ws[wk][wc] = *(const float4*)&W1[(size_t)(k0 + wk) * HIDDEN + wc];
        __syncthreads();
        #pragma unroll
        for (int k = 0; k < 16; k++) {
            float4 a0 = *(const float4*)&As[k][ty * 8];
            float4 a1 = *(const float4*)&As[k][ty * 8 + 4];
            ulonglong2 bp01 = *(const ulonglong2*)&Ws[k][tx * 8];
            ulonglong2 bp23 = *(const ulonglong2*)&Ws[k][tx * 8 + 4];
            float av[8] = {a0.x, a0.y, a0.z, a0.w, a1.x, a1.y, a1.z, a1.w};
            #pragma unroll
            for (int i = 0; i < 8; i++) {
                unsigned long long ad = pack2(av[i], av[i]);
                ffma2(acc[i][0], ad, bp01.x);
                ffma2(acc[i][1], ad, bp01.y);
                ffma2(acc[i][2], ad, bp23.x);
                ffma2(acc[i][3], ad, bp23.y);
            }
        }
        __syncthreads();
    }

    float4 bb0 = *(const float4*)&b1[tx * 8];
    float4 bb1 = *(const float4*)&b1[tx * 8 + 4];
    #pragma unroll
    for (int i = 0; i < 8; i++) {
        int node = bn + ty * 8 + i;
        if (node >= n) break;
        float2 p0 = unpack2(acc[i][0]);
        float2 p1 = unpack2(acc[i][1]);
        float2 p2 = unpack2(acc[i][2]);
        float2 p3 = unpack2(acc[i][3]);
        float4 o0, o1;
        o0.x = fmaxf(p0.x + bb0.x, 0.f);
        o0.y = fmaxf(p0.y + bb0.y, 0.f);
        o0.z = fmaxf(p1.x + bb0.z, 0.f);
        o0.w = fmaxf(p1.y + bb0.w, 0.f);
        o1.x = fmaxf(p2.x + bb1.x, 0.f);
        o1.y = fmaxf(p2.y + bb1.y, 0.f);
        o1.z = fmaxf(p3.x + bb1.z, 0.f);
        o1.w = fmaxf(p3.y + bb1.w, 0.f);
        g_hidden[(size_t)node * 16 + tx * 2]     = o0;
        g_hidden[(size_t)node * 16 + tx * 2 + 1] = o1;
    }
}

// ---------------- MLP layer 2: h0 -> u-space seeds --------------------------
__global__ void mlp2_kernel(const float* __restrict__ W2,
                            const float* __restrict__ b2, int n) {
    __shared__ float w[HIDDEN * CLASSES];
    __shared__ float bs[CLASSES];
    int tid = threadIdx.x;
    for (int i = tid; i < HIDDEN * CLASSES; i += 256) w[i] = W2[i];
    if (tid < CLASSES) bs[tid] = b2[tid];
    __syncthreads();
    int lane = tid & 31;
    int warp = tid >> 5;
    int node0 = (blockIdx.x * 8 + warp) * 4;
    const float* hid = (const float*)g_hidden;
    float* h0u = (float*)g_h0u;
    __half* uA = (__half*)g_uhA;
    #pragma unroll
    for (int t = 0; t < 4; t++) {
        int node = node0 + t;
        if (node >= n) break;
        const float* hr = &hid[(size_t)node * HIDDEN];
        float s = 0.f;
        #pragma unroll
        for (int k = 0; k < HIDDEN; k++)
            s = fmaf(hr[k], w[k * CLASSES + lane], s);
        s += bs[lane];
        float rv = g_rinv[node];
        h0u[(size_t)node * CLASSES + lane] = 0.1f * rv * s;
        uA[(size_t)node * CLASSES + lane]  = __float2half_rn(rv * s);
    }
}

// ---------------- propagation (u-space, fp16 rows, fp32 accumulate) ---------
// u_out[i] = (0.9/deg_i) * sum_{j->i} u[j] + 0.1*rinv_i*h0[i]
// One warp per dst node: 4 edge-groups x 8 lanes; each lane one uint2 (4 halves
// = 4 classes). Only 2 shuffle-reduce levels; 4 independent csr->gather chains.
__global__ void prop_kernel(int parity, float* __restrict__ ext_out, int n) {
    int gw = (blockIdx.x * blockDim.x + threadIdx.x) >> 5;
    if (gw >= n) return;
    int lane = threadIdx.x & 31;
    int grp  = lane >> 3;          // 0..3 edge slot
    int c    = lane & 7;           // 0..7 half4 column

    const uint2* u_in = parity ? g_uhB : g_uhA;
    int beg = gw ? __ldg(&g_rowptr[gw - 1]) : 0;
    int end = __ldg(&g_rowptr[gw]);

    float4 a0 = make_float4(0.f, 0.f, 0.f, 0.f);
    float4 a1 = a0, a2 = a0, a3 = a0;
    int i = beg + grp;
    for (; i + 12 < end; i += 16) {
        int s0 = __ldg(&g_csrs[i]);
        int s1 = __ldg(&g_csrs[i + 4]);
        int s2 = __ldg(&g_csrs[i + 8]);
        int s3 = __ldg(&g_csrs[i + 12]);
        uint2 v0 = __ldg(&u_in[(size_t)s0 * 8 + c]);
        uint2 v1 = __ldg(&u_in[(size_t)s1 * 8 + c]);
        uint2 v2 = __ldg(&u_in[(size_t)s2 * 8 + c]);
        uint2 v3 = __ldg(&u_in[(size_t)s3 * 8 + c]);
        acc4(a0, v0);
        acc4(a1, v1);
        acc4(a2, v2);
        acc4(a3, v3);
    }
    for (; i < end; i += 4) {
        int s0 = __ldg(&g_csrs[i]);
        uint2 v0 = __ldg(&u_in[(size_t)s0 * 8 + c]);
        acc4(a0, v0);
    }
    a0.x += a1.x; a0.y += a1.y; a0.z += a1.z; a0.w += a1.w;
    a2.x += a3.x; a2.y += a3.y; a2.z += a3.z; a2.w += a3.w;
    a0.x += a2.x; a0.y += a2.y; a0.z += a2.z; a0.w += a2.w;

    // reduce across the 4 edge-groups (lanes c, c+8, c+16, c+24): 2 levels
    #pragma unroll
    for (int off = 8; off <= 16; off <<= 1) {
        a0.x += __shfl_xor_sync(0xffffffffu, a0.x, off);
        a0.y += __shfl_xor_sync(0xffffffffu, a0.y, off);
        a0.z += __shfl_xor_sync(0xffffffffu, a0.z, off);
        a0.w += __shfl_xor_sync(0xffffffffu, a0.w, off);
    }
    if (grp == 0) {
        float2 cf = __ldg(&g_coef[gw]);
        float4 z = __ldg(&g_h0u[(size_t)gw * 8 + c]);
        float4 o;
        o.x = fmaf(cf.x, a0.x, z.x);
        o.y = fmaf(cf.x, a0.y, z.y);
        o.z = fmaf(cf.x, a0.z, z.z);
        o.w = fmaf(cf.x, a0.w, z.w);
        if (ext_out) {  // final iteration: back to h-space, fp32 out
            o.x *= cf.y; o.y *= cf.y; o.z *= cf.y; o.w *= cf.y;
            ((float4*)ext_out)[(size_t)gw * 8 + c] = o;
        } else {
            uint2* u_out = parity ? g_uhA : g_uhB;
            u_out[(size_t)gw * 8 + c] = pack4(o);
        }
    }
}

// ---------------- host driver -----------------------------------------------
extern "C" void kernel_launch(void* const* d_in, const int* in_sizes, int n_in,
                              void* d_out, int out_size) {
    const float* x     = (const float*)d_in[0];
    const int*   edges = (const int*)d_in[1];     // int32 (JAX x64 off)
    const float* W1    = (const float*)d_in[2];
    const float* b1    = (const float*)d_in[3];
    const float* W2    = (const float*)d_in[4];
    const float* b2    = (const float*)d_in[5];

    int n = in_sizes[0] / FEATS;
    int E = in_sizes[1] / 2;

    const int TB = 256;
    int nchunks = (n + SCAN_CHUNK - 1) / SCAN_CHUNK;
    zero_kernel<<<(n + TB - 1) / TB, TB>>>(n);
    deg_kernel<<<(E + TB - 1) / TB, TB>>>(edges, E);
    coef_kernel<<<(n + TB - 1) / TB, TB>>>(n);
    scan_block_kernel<<<nchunks, SCAN_CHUNK>>>(n);
    scan_sums_kernel<<<1, 1>>>(nchunks, n);
    scan_add_kernel<<<(n + SCAN_CHUNK - 1) / SCAN_CHUNK, SCAN_CHUNK>>>(n);
    fill_kernel<<<(E + TB - 1) / TB, TB>>>(edges, E);

    mlp1_kernel<<<(n + 255) / 256, 256>>>(x, W1, b1, n);
    mlp2_kernel<<<(n + 31) / 32, 256>>>(W2, b2, n);

    int prop_blocks = (n * 32 + TB - 1) / TB;   // one warp per node
    for (int it = 0; it < 10; it++) {
        prop_kernel<<<prop_blocks, TB>>>(it & 1,
                                         (it == 9) ? (float*)d_out : nullptr,
                                         n);
    }
}

// round 13
// speedup vs baseline: 1.0292x; 1.0292x over previous
#include <cuda_runtime.h>
#include <cuda_fp16.h>

// ---------------- problem constants ----------------------------------------
#define NMAX   100000
#define EMAX   3200000
#define FEATS  512
#define HIDDEN 64
#define CLASSES 32
#define SCAN_CHUNK 1024
#define MAX_CHUNKS ((NMAX + SCAN_CHUNK - 1) / SCAN_CHUNK)

// ---------------- scratch (static device memory; no allocation) ------------
__device__ int    g_deg[NMAX];
__device__ int    g_rowptr[NMAX + 1];     // doubles as fill cursor
__device__ int    g_bsum[MAX_CHUNKS];
__device__ int    g_boff[MAX_CHUNKS];
__device__ int    g_csrs[EMAX];           // src only (u-space: no weights)
__device__ float  g_rinv[NMAX];
__device__ float2 g_coef[NMAX];           // {0.9/deg, sqrt(deg)}
__device__ float4 g_h0u[(size_t)NMAX * 8];      // 0.1 * rinv * h0 (fp32)
__device__ uint4  g_uhA[(size_t)NMAX * 4];      // u as half8 rows (64 B)
__device__ uint4  g_uhB[(size_t)NMAX * 4];

// ---------------- f32x2 packed-FMA helpers (sm_100+) ------------------------
__device__ __forceinline__ unsigned long long pack2(float lo, float hi) {
    unsigned long long r;
    asm("mov.b64 %0, {%1, %2};" : "=l"(r) : "f"(lo), "f"(hi));
    return r;
}
__device__ __forceinline__ void ffma2(unsigned long long& d,
                                      unsigned long long a,
                                      unsigned long long b) {
    asm("fma.rn.f32x2 %0, %1, %2, %0;" : "+l"(d) : "l"(a), "l"(b));
}
__device__ __forceinline__ float2 unpack2(unsigned long long v) {
    float2 f;
    asm("mov.b64 {%0, %1}, %2;" : "=f"(f.x), "=f"(f.y) : "l"(v));
    return f;
}

// half8 helpers
__device__ __forceinline__ void acc8(float4& lo, float4& hi, uint4 v) {
    float2 p;
    p = __half22float2(*(__half2*)&v.x); lo.x += p.x; lo.y += p.y;
    p = __half22float2(*(__half2*)&v.y); lo.z += p.x; lo.w += p.y;
    p = __half22float2(*(__half2*)&v.z); hi.x += p.x; hi.y += p.y;
    p = __half22float2(*(__half2*)&v.w); hi.z += p.x; hi.w += p.y;
}
__device__ __forceinline__ uint4 pack8(float4 lo, float4 hi) {
    uint4 r;
    *(__half2*)&r.x = __floats2half2_rn(lo.x, lo.y);
    *(__half2*)&r.y = __floats2half2_rn(lo.z, lo.w);
    *(__half2*)&r.z = __floats2half2_rn(hi.x, hi.y);
    *(__half2*)&r.w = __floats2half2_rn(hi.z, hi.w);
    return r;
}

// ---------------- setup kernels ---------------------------------------------
__global__ void zero_kernel(int n) {
    int i = blockIdx.x * blockDim.x + threadIdx.x;
    if (i < n) g_deg[i] = 0;
}

// 4 edges per thread (int4). Tail handled by first threads.
__global__ void deg_kernel(const int* __restrict__ edges, int E) {
    int i = blockIdx.x * blockDim.x + threadIdx.x;
    int E4 = E >> 2;
    const int4* dst4 = (const int4*)(edges + E);   // E%4==0 -> 16B aligned
    if (i < E4) {
        int4 d = __ldg(&dst4[i]);
        atomicAdd(&g_deg[d.x], 1);
        atomicAdd(&g_deg[d.y], 1);
        atomicAdd(&g_deg[d.z], 1);
        atomicAdd(&g_deg[d.w], 1);
    }
    int tail = E & 3;
    if (i < tail) atomicAdd(&g_deg[edges[E + E4 * 4 + i]], 1);
}

// ---- decoupled scan phase 1: per-block exclusive scan + block sum + coef ---
__global__ void scan_block_kernel(int n) {
    __shared__ int wsum[32];
    int tid = threadIdx.x, lane = tid & 31, wid = tid >> 5;
    int i = blockIdx.x * SCAN_CHUNK + tid;
    int v = (i < n) ? g_deg[i] : 0;
    if (i < n) {  // fold coef computation here (deg already in hand)
        float fd = (float)max(v, 1);
        g_rinv[i] = rsqrtf(fd);
        g_coef[i] = make_float2(0.9f / fd, sqrtf(fd));
    }
    int s = v;
    #pragma unroll
    for (int o = 1; o < 32; o <<= 1) {
        int t = __shfl_up_sync(0xffffffffu, s, o);
        if (lane >= o) s += t;
    }
    if (lane == 31) wsum[wid] = s;
    __syncthreads();
    if (wid == 0) {
        int ws = wsum[lane];
        #pragma unroll
        for (int o = 1; o < 32; o <<= 1) {
            int t = __shfl_up_sync(0xffffffffu, ws, o);
            if (lane >= o) ws += t;
        }
        wsum[lane] = ws;
    }
    __syncthreads();
    int incl = s + (wid ? wsum[wid - 1] : 0);
    if (i < n) g_rowptr[i] = incl - v;
    if (tid == SCAN_CHUNK - 1) g_bsum[blockIdx.x] = incl;
}

__global__ void scan_sums_kernel(int nb, int n) {
    int acc = 0;
    for (int b = 0; b < nb; b++) {
        g_boff[b] = acc;
        acc += g_bsum[b];
    }
    g_rowptr[n] = acc;
}

__global__ void scan_add_kernel(int n) {
    int i = blockIdx.x * blockDim.x + threadIdx.x;
    if (i < n) g_rowptr[i] += g_boff[i >> 10];
}

// 4 edges per thread (int4)
__global__ void fill_kernel(const int* __restrict__ edges, int E) {
    int i = blockIdx.x * blockDim.x + threadIdx.x;
    int E4 = E >> 2;
    const int4* src4 = (const int4*)edges;
    const int4* dst4 = (const int4*)(edges + E);
    if (i < E4) {
        int4 s = __ldg(&src4[i]);
        int4 d = __ldg(&dst4[i]);
        g_csrs[atomicAdd(&g_rowptr[d.x], 1)] = s.x;
        g_csrs[atomicAdd(&g_rowptr[d.y], 1)] = s.y;
        g_csrs[atomicAdd(&g_rowptr[d.z], 1)] = s.z;
        g_csrs[atomicAdd(&g_rowptr[d.w], 1)] = s.w;
    }
    int tail = E & 3;
    if (i < tail) {
        int s = edges[E4 * 4 + i];
        int d = edges[E + E4 * 4 + i];
        g_csrs[atomicAdd(&g_rowptr[d], 1)] = s;
    }
}

// ---------------- fused MLP: h0 = relu(x@W1+b1)@W2 + b2, write u seeds ------
// Phase A: 256-node x 64-hidden FFMA2 GEMM (8x8 per thread).
// Phase B: per 128-node half-tile, stage hidden in SMEM (aliasing As/Ws),
//          compute @W2+b2, write h0u (fp32) and uA (half8) seeds.
__global__ __launch_bounds__(256, 2)
void mlp_fused_kernel(const float* __restrict__ x,
                      const float* __restrict__ W1,
                      const float* __restrict__ b1,
                      const float* __restrict__ W2,
                      const float* __restrict__ b2, int n) {
    __shared__ float sh[8192];     // 32 KB: [As 16x256 | Ws 16x64] then Hs 128x64
    __shared__ float W2s[HIDDEN * CLASSES];  // 8 KB
    __shared__ float b2s[CLASSES];
    float* As = sh;                // [k][node] : k*256+node
    float* Ws = sh + 4096;         // [k][hid]  : k*64+hid

    int tid = threadIdx.x;
    int tx  = tid & 7;
    int ty  = tid >> 3;
    int bn  = blockIdx.x * 256;

    for (int i = tid; i < HIDDEN * CLASSES; i += 256) W2s[i] = W2[i];
    if (tid < CLASSES) b2s[tid] = b2[tid];

    int anode = tid >> 2;
    int ak    = (tid & 3) * 4;
    int wk    = tid >> 4;
    int wc    = (tid & 15) * 4;

    unsigned long long acc[8][4];
    #pragma unroll
    for (int i = 0; i < 8; i++)
        #pragma unroll
        for (int j = 0; j < 4; j++) acc[i][j] = 0ULL;

    for (int k0 = 0; k0 < FEATS; k0 += 16) {
        #pragma unroll
        for (int r = 0; r < 4; r++) {
            int nd = anode + r * 64;
            int node = bn + nd;
            float4 av = make_float4(0.f, 0.f, 0.f, 0.f);
            if (node < n)
                av = *(const float4*)&x[(size_t)node * FEATS + k0 + ak];
            As[(ak + 0) * 256 + nd] = av.x;
            As[(ak + 1) * 256 + nd] = av.y;
            As[(ak + 2) * 256 + nd] = av.z;
            As[(ak + 3) * 256 + nd] = av.w;
        }
        *(float4*)&Ws[wk * 64 + wc] = *(const float4*)&W1[(size_t)(k0 + wk) * HIDDEN + wc];
        __syncthreads();
        #pragma unroll
        for (int k = 0; k < 16; k++) {
            float4 a0 = *(const float4*)&As[k * 256 + ty * 8];
            float4 a1 = *(const float4*)&As[k * 256 + ty * 8 + 4];
            ulonglong2 bp01 = *(const ulonglong2*)&Ws[k * 64 + tx * 8];
            ulonglong2 bp23 = *(const ulonglong2*)&Ws[k * 64 + tx * 8 + 4];
            float av[8] = {a0.x, a0.y, a0.z, a0.w, a1.x, a1.y, a1.z, a1.w};
            #pragma unroll
            for (int i = 0; i < 8; i++) {
                unsigned long long ad = pack2(av[i], av[i]);
                ffma2(acc[i][0], ad, bp01.x);
                ffma2(acc[i][1], ad, bp01.y);
                ffma2(acc[i][2], ad, bp23.x);
                ffma2(acc[i][3], ad, bp23.y);
            }
        }
        __syncthreads();   // last sync frees As/Ws for Hs aliasing
    }

    float4 bb0 = *(const float4*)&b1[tx * 8];
    float4 bb1 = *(const float4*)&b1[tx * 8 + 4];
    int lane = tid & 31;
    int w    = tid >> 5;
    float* h0u = (float*)g_h0u;
    __half* uA = (__half*)g_uhA;

    #pragma unroll 1
    for (int h = 0; h < 2; h++) {
        // store phase: threads owning this half write relu(acc+bias) to Hs
        if ((ty >> 4) == h) {
            int lty = ty & 15;
            #pragma unroll
            for (int i = 0; i < 8; i++) {
                int ln = lty * 8 + i;
                if (bn + h * 128 + ln < n) {
                    float2 p0 = unpack2(acc[i][0]);
                    float2 p1 = unpack2(acc[i][1]);
                    float2 p2 = unpack2(acc[i][2]);
                    float2 p3 = unpack2(acc[i][3]);
                    float* hr = &sh[ln * 64 + tx * 8];
                    hr[0] = fmaxf(p0.x + bb0.x, 0.f);
                    hr[1] = fmaxf(p0.y + bb0.y, 0.f);
                    hr[2] = fmaxf(p1.x + bb0.z, 0.f);
                    hr[3] = fmaxf(p1.y + bb0.w, 0.f);
                    hr[4] = fmaxf(p2.x + bb1.x, 0.f);
                    hr[5] = fmaxf(p2.y + bb1.y, 0.f);
                    hr[6] = fmaxf(p3.x + bb1.z, 0.f);
                    hr[7] = fmaxf(p3.y + bb1.w, 0.f);
                }
            }
        }
        __syncthreads();
        // compute phase: 8 warps x 16 nodes; lane = class
        #pragma unroll 1
        for (int t = 0; t < 16; t++) {
            int ln = w * 16 + t;
            int node = bn + h * 128 + ln;
            if (node < n) {
                float s = 0.f;
                #pragma unroll
                for (int k4 = 0; k4 < 16; k4++) {
                    float4 hv = *(const float4*)&sh[ln * 64 + k4 * 4];
                    s = fmaf(hv.x, W2s[(k4 * 4 + 0) * CLASSES + lane], s);
                    s = fmaf(hv.y, W2s[(k4 * 4 + 1) * CLASSES + lane], s);
                    s = fmaf(hv.z, W2s[(k4 * 4 + 2) * CLASSES + lane], s);
                    s = fmaf(hv.w, W2s[(k4 * 4 + 3) * CLASSES + lane], s);
                }
                s += b2s[lane];
                float rv = g_rinv[node];
                h0u[(size_t)node * CLASSES + lane] = 0.1f * rv * s;
                uA[(size_t)node * CLASSES + lane]  = __float2half_rn(rv * s);
            }
        }
        __syncthreads();
    }
}

// ---------------- propagation (u-space, fp16 rows, fp32 accumulate) ---------
// One warp per dst node: 8 edge-groups x 4 lanes; lane owns one uint4 (8 halves).
// (R10 mapping — measured best.)
__global__ void prop_kernel(int parity, float* __restrict__ ext_out, int n) {
    int gw = (blockIdx.x * blockDim.x + threadIdx.x) >> 5;
    if (gw >= n) return;
    int lane = threadIdx.x & 31;
    int grp  = lane >> 2;          // 0..7 edge slot
    int c    = lane & 3;           // 0..3 half8 column

    const uint4* u_in = parity ? g_uhB : g_uhA;
    int beg = gw ? __ldg(&g_rowptr[gw - 1]) : 0;
    int end = __ldg(&g_rowptr[gw]);

    float4 lo0 = make_float4(0.f, 0.f, 0.f, 0.f), hi0 = lo0;
    float4 lo1 = lo0, hi1 = lo0;
    int i = beg + grp;
    for (; i + 8 < end; i += 16) {
        int s0 = __ldg(&g_csrs[i]);
        int s1 = __ldg(&g_csrs[i + 8]);
        uint4 v0 = __ldg(&u_in[(size_t)s0 * 4 + c]);
        uint4 v1 = __ldg(&u_in[(size_t)s1 * 4 + c]);
        acc8(lo0, hi0, v0);
        acc8(lo1, hi1, v1);
    }
    if (i < end) {
        int s0 = __ldg(&g_csrs[i]);
        uint4 v0 = __ldg(&u_in[(size_t)s0 * 4 + c]);
        acc8(lo0, hi0, v0);
    }
    lo0.x += lo1.x; lo0.y += lo1.y; lo0.z += lo1.z; lo0.w += lo1.w;
    hi0.x += hi1.x; hi0.y += hi1.y; hi0.z += hi1.z; hi0.w += hi1.w;

    #pragma unroll
    for (int off = 4; off <= 16; off <<= 1) {
        lo0.x += __shfl_xor_sync(0xffffffffu, lo0.x, off);
        lo0.y += __shfl_xor_sync(0xffffffffu, lo0.y, off);
        lo0.z += __shfl_xor_sync(0xffffffffu, lo0.z, off);
        lo0.w += __shfl_xor_sync(0xffffffffu, lo0.w, off);
        hi0.x += __shfl_xor_sync(0xffffffffu, hi0.x, off);
        hi0.y += __shfl_xor_sync(0xffffffffu, hi0.y, off);
        hi0.z += __shfl_xor_sync(0xffffffffu, hi0.z, off);
        hi0.w += __shfl_xor_sync(0xffffffffu, hi0.w, off);
    }
    if (grp == 0) {
        float2 cf = __ldg(&g_coef[gw]);
        float4 z0 = __ldg(&g_h0u[(size_t)gw * 8 + c * 2]);
        float4 z1 = __ldg(&g_h0u[(size_t)gw * 8 + c * 2 + 1]);
        float4 o0, o1;
        o0.x = fmaf(cf.x, lo0.x, z0.x);
        o0.y = fmaf(cf.x, lo0.y, z0.y);
        o0.z = fmaf(cf.x, lo0.z, z0.z);
        o0.w = fmaf(cf.x, lo0.w, z0.w);
        o1.x = fmaf(cf.x, hi0.x, z1.x);
        o1.y = fmaf(cf.x, hi0.y, z1.y);
        o1.z = fmaf(cf.x, hi0.z, z1.z);
        o1.w = fmaf(cf.x, hi0.w, z1.w);
        if (ext_out) {  // final iteration: back to h-space, fp32 out
            o0.x *= cf.y; o0.y *= cf.y; o0.z *= cf.y; o0.w *= cf.y;
            o1.x *= cf.y; o1.y *= cf.y; o1.z *= cf.y; o1.w *= cf.y;
            ((float4*)ext_out)[(size_t)gw * 8 + c * 2]     = o0;
            ((float4*)ext_out)[(size_t)gw * 8 + c * 2 + 1] = o1;
        } else {
            uint4* u_out = parity ? g_uhA : g_uhB;
            u_out[(size_t)gw * 4 + c] = pack8(o0, o1);
        }
    }
}

// ---------------- host driver -----------------------------------------------
extern "C" void kernel_launch(void* const* d_in, const int* in_sizes, int n_in,
                              void* d_out, int out_size) {
    const float* x     = (const float*)d_in[0];
    const int*   edges = (const int*)d_in[1];     // int32 (JAX x64 off)
    const float* W1    = (const float*)d_in[2];
    const float* b1    = (const float*)d_in[3];
    const float* W2    = (const float*)d_in[4];
    const float* b2    = (const float*)d_in[5];

    int n = in_sizes[0] / FEATS;
    int E = in_sizes[1] / 2;

    const int TB = 256;
    int nchunks = (n + SCAN_CHUNK - 1) / SCAN_CHUNK;
    int E4 = (E >> 2) ? (E >> 2) : 1;
    zero_kernel<<<(n + TB - 1) / TB, TB>>>(n);
    deg_kernel<<<(E4 + TB - 1) / TB, TB>>>(edges, E);
    scan_block_kernel<<<nchunks, SCAN_CHUNK>>>(n);
    scan_sums_kernel<<<1, 1>>>(nchunks, n);
    scan_add_kernel<<<(n + SCAN_CHUNK - 1) / SCAN_CHUNK, SCAN_CHUNK>>>(n);
    fill_kernel<<<(E4 + TB - 1) / TB, TB>>>(edges, E);

    mlp_fused_kernel<<<(n + 255) / 256, 256>>>(x, W1, b1, W2, b2, n);

    int prop_blocks = (n * 32 + TB - 1) / TB;   // one warp per node
    for (int it = 0; it < 10; it++) {
        prop_kernel<<<prop_blocks, TB>>>(it & 1,
                                         (it == 9) ? (float*)d_out : nullptr,
                                         n);
    }
}